// round 13
// baseline (speedup 1.0000x reference)
#include <cuda_runtime.h>
#include <math.h>

#define NIMG 256        // B*N = 64*4
#define NT 512
#define NWARP 16

typedef unsigned long long ull;

// precomputed pupil: (mag*cos(ph), mag*sin(ph), prop, 0) for a,b in [8,57)
__device__ float4 g_pupil[49 * 49];

// ---- dynamic shared layout (bytes), compact-column SGDG (160 slots) ----
#define SM_CSB  0                    // float2 [49]            = 512 (padded)
#define SM_SDB  (SM_CSB + 512)       // float4 [49][24]        = 18816
#define SM_WT   (SM_SDB + 18816)     // float2 [256]           = 2048
#define SM_WP   (SM_WT + 2048)       // ulonglong2 [256]       = 4096
#define SM_SGDG (SM_WP + 4096)       // float4 [24][160]       = 61440
#define SM_G0   (SM_SGDG + 61440)    // float2 [160]           = 1280
#define SM_CROP (SM_G0 + 1280)       // float  [4096]          = 16384
#define SM_RED  (SM_CROP + 16384)    // float  [16]            = 64
#define SM_TOTAL (SM_RED + 64)       // 104640 bytes

#define SGSTRIDE 160

extern __shared__ char smem_raw[];

#define FMA2(d, a, b, c) \
    asm("fma.rn.f32x2 %0, %1, %2, %3;" : "=l"(d) : "l"(a), "l"(b), "l"(c))

__device__ __forceinline__ float2 u2f2(ull v) {
    float2 r;
    asm("mov.b64 {%0, %1}, %2;" : "=f"(r.x), "=f"(r.y) : "l"(v));
    return r;
}
__device__ __forceinline__ ull splat2(float f) {
    ull r;
    asm("mov.b64 %0, {%1, %1};" : "=l"(r) : "f"(f));
    return r;
}

__global__ void prep_kernel(const float* __restrict__ ph)
{
    int idx = blockIdx.x * blockDim.x + threadIdx.x;
    if (idx >= 49 * 49) return;
    int ar = idx / 49, br = idx - ar * 49;
    int a = ar + 8, b = br + 8;
    float us = (float)(2 * a - 63) * (1.0f / 47.25f);
    float vs = (float)(2 * b - 63) * (1.0f / 47.25f);
    float R2 = us * us + vs * vs;
    float4 o = make_float4(0.0f, 0.0f, 0.0f, 0.0f);
    if (R2 <= 1.0f) {
        float prop = sqrtf(fmaxf(1.0f - R2, 0.0f));
        float s, c;
        sincosf(ph[a * 64 + b], &s, &c);
        o = make_float4(c, s, prop, 0.0f);
    }
    g_pupil[idx] = o;
}

// render-side pupil point: table lookup + one FMA-path sincos, zero MUFU
__device__ __forceinline__ float2 pupil_pt(int a, int b, float dx, float dy,
                                           float z)
{
    float4 t = g_pupil[(a - 8) * 49 + (b - 8)];
    float ang = fmaf(t.z, z, fmaf((float)(a - 32), dx, (float)(b - 32) * dy));
    float sn, cs;
    sincosf(ang, &sn, &cs);
    return make_float2(fmaf(t.x, cs, -(t.y * sn)),
                       fmaf(t.x, sn,  (t.y * cs)));
}

__device__ __forceinline__ int qe_of(int m) {
    int mm = 2 * m - 1;
    float wrad = 2232.5625f - (float)(mm * mm);
    return min(24, (int)((sqrtf(wrad) - 1.0f) * 0.5f) + 2);
}

__global__ void __launch_bounds__(NT, 2)
render_kernel(const float* __restrict__ X,  const float* __restrict__ Y,
              const float* __restrict__ Z,  const float* __restrict__ Aa,
              const float* __restrict__ Bg, const float* __restrict__ P,
              float* __restrict__ out)
{
    float2*     CsB  = (float2*)    (smem_raw + SM_CSB);
    float4*     SDB  = (float4*)    (smem_raw + SM_SDB);
    float2*     Wt   = (float2*)    (smem_raw + SM_WT);
    ulonglong2* Wp   = (ulonglong2*)(smem_raw + SM_WP);
    float4*     SGDG = (float4*)    (smem_raw + SM_SGDG);
    float2*     G0   = (float2*)    (smem_raw + SM_G0);
    float*      crop = (float*)     (smem_raw + SM_CROP);
    float*      red  = (float*)     (smem_raw + SM_RED);

    const int img  = blockIdx.x;
    const int tid  = threadIdx.x;
    const int lane = tid & 31;
    const int warp = tid >> 5;     // 0..15

    const float x = X[img], y = Y[img], z = Z[img];
    const float k2pi = 6.283185307179586f / 256.0f;
    const float dx = -k2pi * x, dy = -k2pi * y;

    // ---- adaptive window geometry (uniform per CTA) ----
    const int iu = (int)(((unsigned)__float2int_rn(x)) & 255u);
    const int iv = (int)(((unsigned)__float2int_rn(y)) & 255u);
    const float az = fabsf(z);
    const float ru = fminf(40.0f, 12.0f + 6.0f * az);
    const float rv = fminf(48.0f, 12.0f + 6.0f * az);
    const int nu = (int)ceilf(ru * 0.25f);          // u tiles of 8
    const int nv = (int)ceilf(rv * (1.0f / 16.0f)); // v blocks of 32 (<=3)
    const int wu0 = (iu - 4 * nu) & 255;
    const int wv0 = (iv - 16 * nv) & 255;

    // ---- window v-block classification ----
    int cblk0 = (wv0 + 32) & 255;
    int cblk1 = (wv0 + 64) & 255;
    int cblk2 = (wv0 + 96) & 255;
    bool vin0 = (cblk0 <= 32);
    bool vin1 = (cblk1 <= 32);
    bool vin2 = (nv < 3) | (cblk2 <= 32);
    if (nv < 2) vin1 = true;
    int ob0 = -1, ob1 = -1, ob2 = -1, n_out = 0;
    if (!vin0) { ob0 = 0; n_out = 1; }
    if (!vin1) { (n_out == 0 ? ob0 : ob1) = 1; n_out++; }
    if (!vin2) { (n_out == 0 ? ob0 : (n_out == 1 ? ob1 : ob2)) = 2; n_out++; }

    // ---- twiddle tables ----
    if (tid < 256) {
        float s, c;
        sincospif((float)tid * (1.0f / 128.0f), &s, &c);
        Wt[tid] = make_float2(c, s);
        Wp[tid] = make_ulonglong2(splat2(c), splat2(s));
    }

    // ---- fused Phase A + SDB ----
    for (int idx = tid; idx < 49 * 25; idx += NT) {
        int r = idx / 25;
        int q = idx - r * 25;               // 0..24
        int a = r + 8;
        if (q == 0) {
            CsB[r] = pupil_pt(a, 32, dx, dy, z);
        } else {
            float2 cu = pupil_pt(a, 32 + q, dx, dy, z);
            float2 cd = pupil_pt(a, 32 - q, dx, dy, z);
            SDB[r * 24 + (q - 1)] = make_float4(cu.x + cd.x, cu.y + cd.y,
                                                cu.y - cd.y, cu.x - cd.x);
        }
    }
    __syncthreads();

    // ---- Phase B: crop columns + out-of-crop window columns only ----
    const int nb_win = 25 * n_out;
    const int nb_tot = 25 + nb_win + 1;
    for (int i = 0; ; i++) {
        int t = warp + NWARP * i;
        if (t >= nb_tot) break;

        if (t < 25 + nb_win) {
            int m, slot_lo, v;
            bool is_crop = (t < 25);
            if (is_crop) {
                m = t;
                v = lane;                           // 0..31
                slot_lo = 32 + lane;                // tcol(v)
            } else {
                int t2 = t - 25;
                int g  = t2 / 25;
                m = t2 - 25 * g;
                int wvb = (g == 0) ? ob0 : (g == 1) ? ob1 : ob2;
                v = (wv0 + (wvb << 5) + lane) & 255;
                slot_lo = 64 + (wvb << 5) + lane;
            }
            int qe = qe_of(m);

            float2 w0 = Wt[v];
            ull CC  = splat2(w0.x), SS  = splat2(w0.y);
            ull RC  = CC,           RS  = SS;
            ull NRS = splat2(-w0.y);
            const ull ZERO = 0;

            ull ACu = 0, ASu = 0, ACd = 0, ASd = 0;
            const ulonglong2* sup = (const ulonglong2*)(SDB + (24 + m) * 24);
            const ulonglong2* sdn = (const ulonglong2*)(SDB + (24 - m) * 24);

            if (m == 0) {
                #pragma unroll 4
                for (int mb = 0; mb < qe; mb++) {
                    ulonglong2 sv = sup[mb];
                    FMA2(ACu, CC, sv.x, ACu);
                    FMA2(ASu, SS, sv.y, ASu);
                    ull t1, t2;
                    FMA2(t1, CC, RC, ZERO); FMA2(t2, CC, RS, ZERO);
                    FMA2(CC, SS, NRS, t1);  FMA2(SS, SS, RC, t2);
                }
                float2 ac = u2f2(ACu), as = u2f2(ASu);
                float2 base = CsB[24];
                float2 glo = make_float2(base.x + ac.x - as.x,
                                         base.y + ac.y + as.y);
                G0[slot_lo] = glo;
                if (is_crop) {
                    float2 ghi = make_float2(base.x + ac.x + as.x,
                                             base.y + ac.y - as.y);
                    G0[32 - v] = (v == 0) ? glo : ghi;
                }
            } else {
                #pragma unroll 4
                for (int mb = 0; mb < qe; mb++) {
                    ulonglong2 sv = sup[mb];
                    ulonglong2 dv = sdn[mb];
                    FMA2(ACu, CC, sv.x, ACu);
                    FMA2(ASu, SS, sv.y, ASu);
                    FMA2(ACd, CC, dv.x, ACd);
                    FMA2(ASd, SS, dv.y, ASd);
                    ull t1, t2;
                    FMA2(t1, CC, RC, ZERO); FMA2(t2, CC, RS, ZERO);
                    FMA2(CC, SS, NRS, t1);  FMA2(SS, SS, RC, t2);
                }
                float2 acu = u2f2(ACu), asu = u2f2(ASu);
                float2 acd = u2f2(ACd), asd = u2f2(ASd);
                float2 bu = CsB[24 + m];
                float2 bd = CsB[24 - m];
                float2 up_lo = make_float2(bu.x + acu.x - asu.x,
                                           bu.y + acu.y + asu.y);
                float2 dn_lo = make_float2(bd.x + acd.x - asd.x,
                                           bd.y + acd.y + asd.y);
                int base = (m - 1) * SGSTRIDE;
                float4 lo4 = make_float4(up_lo.x + dn_lo.x, up_lo.y + dn_lo.y,
                                         up_lo.y - dn_lo.y, up_lo.x - dn_lo.x);
                SGDG[base + slot_lo] = lo4;
                if (is_crop) {
                    float2 up_hi = make_float2(bu.x + acu.x + asu.x,
                                               bu.y + acu.y - asu.y);
                    float2 dn_hi = make_float2(bd.x + acd.x + asd.x,
                                               bd.y + acd.y - asd.y);
                    float4 hi4 = make_float4(up_hi.x + dn_hi.x,
                                             up_hi.y + dn_hi.y,
                                             up_hi.y - dn_hi.y,
                                             up_hi.x - dn_hi.x);
                    SGDG[base + 32 - v] = (v == 0) ? lo4 : hi4;
                }
            }
        } else if (lane < 25) {
            // ---- scalar v=224 column (tcol slot 0), lane = m ----
            int m = lane;
            int qe = qe_of(m);
            float2 wv = Wt[224];
            float wc = wv.x, ws = wv.y;
            float rc = wc, rs = ws;
            float a1u = 0, a2u = 0, a3u = 0, a4u = 0;
            float a1d = 0, a2d = 0, a3d = 0, a4d = 0;
            const float4* sup = SDB + (24 + m) * 24;
            const float4* sdn = SDB + (24 - m) * 24;
            for (int q = 0; q < qe; q++) {
                float4 s = sup[q];
                a1u = fmaf(wc, s.x, a1u); a2u = fmaf(wc, s.y, a2u);
                a3u = fmaf(ws, s.z, a3u); a4u = fmaf(ws, s.w, a4u);
                float4 d = sdn[q];
                a1d = fmaf(wc, d.x, a1d); a2d = fmaf(wc, d.y, a2d);
                a3d = fmaf(ws, d.z, a3d); a4d = fmaf(ws, d.w, a4d);
                float nc = fmaf(wc, rc, -(ws * rs));
                float ns = fmaf(wc, rs,  (ws * rc));
                wc = nc; ws = ns;
            }
            float2 bu = CsB[24 + m];
            float2 bd = CsB[24 - m];
            float2 up = make_float2(bu.x + a1u - a3u, bu.y + a2u + a4u);
            float2 dn = make_float2(bd.x + a1d - a3d, bd.y + a2d + a4d);
            if (m == 0) {
                G0[0] = up;
            } else {
                SGDG[(m - 1) * SGSTRIDE] =
                    make_float4(up.x + dn.x, up.y + dn.y,
                                up.y - dn.y, up.x - dn.x);
            }
        }
    }
    __syncthreads();

    // ---- Phase C: crop (10 units, tile 8, u-fold)
    //              + window (nu*nv units, tile 8, crop-overlap skipped) ----
    const int nunits = 10 + nu * nv;
    float lmax = 0.0f;
    const char* wp = (const char*)Wp;

    for (int i = 0; ; i++) {
        int t = warp + NWARP * i;
        if (t >= nunits) break;

        bool is_crop = (t < 10);
        int u0, slot;
        if (is_crop) {
            int ut = t >> 1;
            int vb = t & 1;
            slot = (vb << 5) + lane;        // tcol 0..63
            u0 = ut << 3;
        } else {
            int t2  = t - 10;
            int wvb = t2 / nu;
            int wt  = t2 - wvb * nu;
            int ub  = (wu0 + (wt << 3)) & 255;
            int cu  = (ub + 32) & 255;
            bool u_in = (cu <= 56);
            bool v_in = (wvb == 0) ? vin0 : (wvb == 1) ? vin1 : vin2;
            if (u_in && v_in) continue;     // fully covered by crop units
            int cblk = (wvb == 0) ? cblk0 : (wvb == 1) ? cblk1 : cblk2;
            slot = (v_in ? cblk : (64 + (wvb << 5))) + lane;
            u0 = ub;
        }

        int st0 = (((u0 + 0) & 255) << 4), st1 = (((u0 + 1) & 255) << 4);
        int st2 = (((u0 + 2) & 255) << 4), st3 = (((u0 + 3) & 255) << 4);
        int st4 = (((u0 + 4) & 255) << 4), st5 = (((u0 + 5) & 255) << 4);
        int st6 = (((u0 + 6) & 255) << 4), st7 = (((u0 + 7) & 255) << 4);
        int o0 = st0, o1 = st1, o2 = st2, o3 = st3;
        int o4 = st4, o5 = st5, o6 = st6, o7 = st7;
        ull c0 = 0, s0 = 0, c1 = 0, s1 = 0;
        ull c2 = 0, s2 = 0, c3 = 0, s3 = 0;
        ull c4 = 0, s4 = 0, c5 = 0, s5 = 0;
        ull c6 = 0, s6 = 0, c7 = 0, s7 = 0;

        const char* gp = (const char*)(SGDG + slot);
        #pragma unroll 4
        for (int m = 1; m <= 24; m++) {
            ulonglong2 gsd = *(const ulonglong2*)gp;
            gp += SGSTRIDE * 16;
            ulonglong2 w0 = *(const ulonglong2*)(wp + o0);
            ulonglong2 w1 = *(const ulonglong2*)(wp + o1);
            ulonglong2 w2 = *(const ulonglong2*)(wp + o2);
            ulonglong2 w3 = *(const ulonglong2*)(wp + o3);
            FMA2(c0, w0.x, gsd.x, c0); FMA2(s0, w0.y, gsd.y, s0);
            FMA2(c1, w1.x, gsd.x, c1); FMA2(s1, w1.y, gsd.y, s1);
            FMA2(c2, w2.x, gsd.x, c2); FMA2(s2, w2.y, gsd.y, s2);
            FMA2(c3, w3.x, gsd.x, c3); FMA2(s3, w3.y, gsd.y, s3);
            o0 = (o0 + st0) & 4095;
            o1 = (o1 + st1) & 4095;
            o2 = (o2 + st2) & 4095;
            o3 = (o3 + st3) & 4095;
            ulonglong2 w4 = *(const ulonglong2*)(wp + o4);
            ulonglong2 w5 = *(const ulonglong2*)(wp + o5);
            ulonglong2 w6 = *(const ulonglong2*)(wp + o6);
            ulonglong2 w7 = *(const ulonglong2*)(wp + o7);
            FMA2(c4, w4.x, gsd.x, c4); FMA2(s4, w4.y, gsd.y, s4);
            FMA2(c5, w5.x, gsd.x, c5); FMA2(s5, w5.y, gsd.y, s5);
            FMA2(c6, w6.x, gsd.x, c6); FMA2(s6, w6.y, gsd.y, s6);
            FMA2(c7, w7.x, gsd.x, c7); FMA2(s7, w7.y, gsd.y, s7);
            o4 = (o4 + st4) & 4095;
            o5 = (o5 + st5) & 4095;
            o6 = (o6 + st6) & 4095;
            o7 = (o7 + st7) & 4095;
        }

        float2 g0 = G0[slot];
        #pragma unroll
        for (int j = 0; j < 8; j++) {
            ull cj, sj;
            switch (j) {
                case 0: cj = c0; sj = s0; break;
                case 1: cj = c1; sj = s1; break;
                case 2: cj = c2; sj = s2; break;
                case 3: cj = c3; sj = s3; break;
                case 4: cj = c4; sj = s4; break;
                case 5: cj = c5; sj = s5; break;
                case 6: cj = c6; sj = s6; break;
                default: cj = c7; sj = s7; break;
            }
            float2 ac = u2f2(cj);
            float2 as = u2f2(sj);
            float t1r = g0.x + ac.x, t1i = g0.y + ac.y;
            float orx = t1r - as.x, oix = t1i + as.y;   // out(u)
            float p2a = fmaf(orx, orx, oix * oix);
            lmax = fmaxf(lmax, p2a);
            if (is_crop) {
                float prx = t1r + as.x, pix = t1i - as.y; // out(256-u)
                float p2b = fmaf(prx, prx, pix * pix);
                lmax = fmaxf(lmax, p2b);
                int u  = u0 + j;
                int sa = (u + 32) & 255;
                if (sa < 64) crop[(sa << 6) + slot] = p2a;
                int sb = (32 - u) & 255;
                if (sb < 64) crop[(sb << 6) + slot] = p2b;
            }
        }
    }

    // ---- CTA max reduction (16 warps) ----
    #pragma unroll
    for (int o = 16; o > 0; o >>= 1)
        lmax = fmaxf(lmax, __shfl_xor_sync(0xFFFFFFFFu, lmax, o));
    if (lane == 0) red[warp] = lmax;
    __syncthreads();
    if (warp == 0) {
        float m = (lane < NWARP) ? red[lane] : 0.0f;
        #pragma unroll
        for (int o = 8; o > 0; o >>= 1)
            m = fmaxf(m, __shfl_xor_sync(0xFFFFFFFFu, m, o));
        if (lane == 0) red[0] = m;
    }
    __syncthreads();
    const float maxv = red[0];

    // ---- epilogue: atomic-accumulate (psf/max * A + bg) * mask into out[b] ----
    const float A    = Aa[img];
    const float bg   = Bg[img];
    const float mask = (P[img] > 0.5f) ? 1.0f : 0.0f;
    const float scale = (A / maxv) * mask;
    const float bgm   = bg * mask;
    float* outb = out + (size_t)(img >> 2) * 4096;
    #pragma unroll
    for (int k = 0; k < 8; k++) {
        int idx = tid + k * NT;
        atomicAdd(&outb[idx], fmaf(crop[idx], scale, bgm));
    }
}

extern "C" void kernel_launch(void* const* d_in, const int* in_sizes, int n_in,
                              void* d_out, int out_size)
{
    (void)in_sizes; (void)n_in;
    cudaMemsetAsync(d_out, 0, (size_t)out_size * sizeof(float));
    prep_kernel<<<(49 * 49 + 511) / 512, 512>>>((const float*)d_in[6]);
    cudaFuncSetAttribute(render_kernel,
                         cudaFuncAttributeMaxDynamicSharedMemorySize, SM_TOTAL);
    render_kernel<<<NIMG, NT, SM_TOTAL>>>(
        (const float*)d_in[0], (const float*)d_in[1], (const float*)d_in[2],
        (const float*)d_in[3], (const float*)d_in[4], (const float*)d_in[5],
        (float*)d_out);
}

// round 14
// speedup vs baseline: 1.2403x; 1.2403x over previous
#include <cuda_runtime.h>
#include <math.h>

#define NIMG 256        // B*N = 64*4
#define NT 512
#define NWARP 16

typedef unsigned long long ull;

// ---- dynamic shared layout (bytes), compact-column SGDG (160 slots) ----
#define SM_CSB  0                    // float2 [49]            = 512 (padded)
#define SM_SDB  (SM_CSB + 512)       // float4 [49][24]        = 18816
#define SM_WT   (SM_SDB + 18816)     // float2 [256]           = 2048
#define SM_WP   (SM_WT + 2048)       // ulonglong2 [256]       = 4096
#define SM_SGDG (SM_WP + 4096)       // float4 [24][160]       = 61440
#define SM_G0   (SM_SGDG + 61440)    // float2 [160]           = 1280
#define SM_CROP (SM_G0 + 1280)       // float  [4096]          = 16384
#define SM_RED  (SM_CROP + 16384)    // float  [16]            = 64
#define SM_TOTAL (SM_RED + 64)       // 104640 bytes

#define SGSTRIDE 160

extern __shared__ char smem_raw[];

#define FMA2(d, a, b, c) \
    asm("fma.rn.f32x2 %0, %1, %2, %3;" : "=l"(d) : "l"(a), "l"(b), "l"(c))

__device__ __forceinline__ float2 u2f2(ull v) {
    float2 r;
    asm("mov.b64 {%0, %1}, %2;" : "=f"(r.x), "=f"(r.y) : "l"(v));
    return r;
}
__device__ __forceinline__ ull splat2(float f) {
    ull r;
    asm("mov.b64 %0, {%1, %1};" : "=l"(r) : "f"(f));
    return r;
}

__device__ __forceinline__ float2 pupil_pt(int a, int b, float x, float y,
                                           float z, const float* __restrict__ ph)
{
    float us = (float)(2 * a - 63) * (1.0f / 47.25f);
    float vs = (float)(2 * b - 63) * (1.0f / 47.25f);
    float R  = sqrtf(us * us + vs * vs);
    if (R > 1.0f) return make_float2(0.0f, 0.0f);
    float prop = sqrtf(fmaxf(1.0f - R * R, 0.0f));
    float psi = ph[a * 64 + b] + prop * z
              - (6.283185307179586f / 256.0f)
                * ((float)(a - 32) * x + (float)(b - 32) * y);
    float sn, cs;
    __sincosf(psi, &sn, &cs);
    return make_float2(cs, sn);
}

__device__ __forceinline__ int qe_of(int m) {
    int mm = 2 * m - 1;
    float wrad = 2232.5625f - (float)(mm * mm);
    return min(24, (int)((sqrtf(wrad) - 1.0f) * 0.5f) + 2);
}

__global__ void __launch_bounds__(NT, 2)
render_kernel(const float* __restrict__ X,  const float* __restrict__ Y,
              const float* __restrict__ Z,  const float* __restrict__ Aa,
              const float* __restrict__ Bg, const float* __restrict__ P,
              const float* __restrict__ phase0,
              float* __restrict__ out)
{
    float2*     CsB  = (float2*)    (smem_raw + SM_CSB);
    float4*     SDB  = (float4*)    (smem_raw + SM_SDB);
    float2*     Wt   = (float2*)    (smem_raw + SM_WT);
    ulonglong2* Wp   = (ulonglong2*)(smem_raw + SM_WP);
    float4*     SGDG = (float4*)    (smem_raw + SM_SGDG);
    float2*     G0   = (float2*)    (smem_raw + SM_G0);
    float*      crop = (float*)     (smem_raw + SM_CROP);
    float*      red  = (float*)     (smem_raw + SM_RED);

    const int img  = blockIdx.x;
    const int tid  = threadIdx.x;
    const int lane = tid & 31;
    const int warp = tid >> 5;     // 0..15

    const float x = X[img], y = Y[img], z = Z[img];

    // ---- adaptive window geometry (uniform per CTA) ----
    const int iu = (int)(((unsigned)__float2int_rn(x)) & 255u);
    const int iv = (int)(((unsigned)__float2int_rn(y)) & 255u);
    const float az = fabsf(z);
    const float ru = fminf(40.0f, 12.0f + 6.0f * az);
    const float rv = fminf(48.0f, 12.0f + 6.0f * az);
    const int nu = (int)ceilf(ru * 0.5f);           // u tiles of 4
    const int nv = (int)ceilf(rv * (1.0f / 16.0f)); // v blocks of 32 (<=3)
    const int wu0 = (iu - 2 * nu) & 255;
    const int wv0 = (iv - 16 * nv) & 255;

    // ---- window v-block classification ----
    int cblk0 = (wv0 + 32) & 255;
    int cblk1 = (wv0 + 64) & 255;
    int cblk2 = (wv0 + 96) & 255;
    bool vin0 = (cblk0 <= 32);
    bool vin1 = (cblk1 <= 32);
    bool vin2 = (nv < 3) | (cblk2 <= 32);
    if (nv < 2) vin1 = true;
    int ob0 = -1, ob1 = -1, ob2 = -1, n_out = 0;
    if (!vin0) { ob0 = 0; n_out = 1; }
    if (!vin1) { (n_out == 0 ? ob0 : ob1) = 1; n_out++; }
    if (!vin2) { (n_out == 0 ? ob0 : (n_out == 1 ? ob1 : ob2)) = 2; n_out++; }

    // ---- twiddle tables ----
    if (tid < 256) {
        float s, c;
        sincospif((float)tid * (1.0f / 128.0f), &s, &c);
        Wt[tid] = make_float2(c, s);
        Wp[tid] = make_ulonglong2(splat2(c), splat2(s));
    }

    // ---- fused Phase A + SDB ----
    for (int idx = tid; idx < 49 * 25; idx += NT) {
        int r = idx / 25;
        int q = idx - r * 25;               // 0..24
        int a = r + 8;
        if (q == 0) {
            CsB[r] = pupil_pt(a, 32, x, y, z, phase0);
        } else {
            float2 cu = pupil_pt(a, 32 + q, x, y, z, phase0);
            float2 cd = pupil_pt(a, 32 - q, x, y, z, phase0);
            SDB[r * 24 + (q - 1)] = make_float4(cu.x + cd.x, cu.y + cd.y,
                                                cu.y - cd.y, cu.x - cd.x);
        }
    }
    __syncthreads();

    // ---- Phase B: crop columns + out-of-crop window columns only ----
    const int nb_win = 25 * n_out;
    const int nb_tot = 25 + nb_win + 1;
    for (int i = 0; ; i++) {
        int t = warp + NWARP * i;
        if (t >= nb_tot) break;

        if (t < 25 + nb_win) {
            int m, slot_lo, v;
            bool is_crop = (t < 25);
            if (is_crop) {
                m = t;
                v = lane;                           // 0..31
                slot_lo = 32 + lane;                // tcol(v)
            } else {
                int t2 = t - 25;
                int g  = t2 / 25;
                m = t2 - 25 * g;
                int wvb = (g == 0) ? ob0 : (g == 1) ? ob1 : ob2;
                v = (wv0 + (wvb << 5) + lane) & 255;
                slot_lo = 64 + (wvb << 5) + lane;
            }
            int qe = qe_of(m);

            float2 w0 = Wt[v];
            ull CC  = splat2(w0.x), SS  = splat2(w0.y);
            ull RC  = CC,           RS  = SS;
            ull NRS = splat2(-w0.y);
            const ull ZERO = 0;

            ull ACu = 0, ASu = 0, ACd = 0, ASd = 0;
            const ulonglong2* sup = (const ulonglong2*)(SDB + (24 + m) * 24);
            const ulonglong2* sdn = (const ulonglong2*)(SDB + (24 - m) * 24);

            if (m == 0) {
                #pragma unroll 4
                for (int mb = 0; mb < qe; mb++) {
                    ulonglong2 sv = sup[mb];
                    FMA2(ACu, CC, sv.x, ACu);
                    FMA2(ASu, SS, sv.y, ASu);
                    ull t1, t2;
                    FMA2(t1, CC, RC, ZERO); FMA2(t2, CC, RS, ZERO);
                    FMA2(CC, SS, NRS, t1);  FMA2(SS, SS, RC, t2);
                }
                float2 ac = u2f2(ACu), as = u2f2(ASu);
                float2 base = CsB[24];
                float2 glo = make_float2(base.x + ac.x - as.x,
                                         base.y + ac.y + as.y);
                G0[slot_lo] = glo;
                if (is_crop) {
                    float2 ghi = make_float2(base.x + ac.x + as.x,
                                             base.y + ac.y - as.y);
                    G0[32 - v] = (v == 0) ? glo : ghi;
                }
            } else {
                #pragma unroll 4
                for (int mb = 0; mb < qe; mb++) {
                    ulonglong2 sv = sup[mb];
                    ulonglong2 dv = sdn[mb];
                    FMA2(ACu, CC, sv.x, ACu);
                    FMA2(ASu, SS, sv.y, ASu);
                    FMA2(ACd, CC, dv.x, ACd);
                    FMA2(ASd, SS, dv.y, ASd);
                    ull t1, t2;
                    FMA2(t1, CC, RC, ZERO); FMA2(t2, CC, RS, ZERO);
                    FMA2(CC, SS, NRS, t1);  FMA2(SS, SS, RC, t2);
                }
                float2 acu = u2f2(ACu), asu = u2f2(ASu);
                float2 acd = u2f2(ACd), asd = u2f2(ASd);
                float2 bu = CsB[24 + m];
                float2 bd = CsB[24 - m];
                float2 up_lo = make_float2(bu.x + acu.x - asu.x,
                                           bu.y + acu.y + asu.y);
                float2 dn_lo = make_float2(bd.x + acd.x - asd.x,
                                           bd.y + acd.y + asd.y);
                int base = (m - 1) * SGSTRIDE;
                float4 lo4 = make_float4(up_lo.x + dn_lo.x, up_lo.y + dn_lo.y,
                                         up_lo.y - dn_lo.y, up_lo.x - dn_lo.x);
                SGDG[base + slot_lo] = lo4;
                if (is_crop) {
                    float2 up_hi = make_float2(bu.x + acu.x + asu.x,
                                               bu.y + acu.y - asu.y);
                    float2 dn_hi = make_float2(bd.x + acd.x + asd.x,
                                               bd.y + acd.y - asd.y);
                    float4 hi4 = make_float4(up_hi.x + dn_hi.x,
                                             up_hi.y + dn_hi.y,
                                             up_hi.y - dn_hi.y,
                                             up_hi.x - dn_hi.x);
                    SGDG[base + 32 - v] = (v == 0) ? lo4 : hi4;
                }
            }
        } else if (lane < 25) {
            // ---- scalar v=224 column (tcol slot 0), lane = m ----
            int m = lane;
            int qe = qe_of(m);
            float2 wv = Wt[224];
            float wc = wv.x, ws = wv.y;
            float rc = wc, rs = ws;
            float a1u = 0, a2u = 0, a3u = 0, a4u = 0;
            float a1d = 0, a2d = 0, a3d = 0, a4d = 0;
            const float4* sup = SDB + (24 + m) * 24;
            const float4* sdn = SDB + (24 - m) * 24;
            for (int q = 0; q < qe; q++) {
                float4 s = sup[q];
                a1u = fmaf(wc, s.x, a1u); a2u = fmaf(wc, s.y, a2u);
                a3u = fmaf(ws, s.z, a3u); a4u = fmaf(ws, s.w, a4u);
                float4 d = sdn[q];
                a1d = fmaf(wc, d.x, a1d); a2d = fmaf(wc, d.y, a2d);
                a3d = fmaf(ws, d.z, a3d); a4d = fmaf(ws, d.w, a4d);
                float nc = fmaf(wc, rc, -(ws * rs));
                float ns = fmaf(wc, rs,  (ws * rc));
                wc = nc; ws = ns;
            }
            float2 bu = CsB[24 + m];
            float2 bd = CsB[24 - m];
            float2 up = make_float2(bu.x + a1u - a3u, bu.y + a2u + a4u);
            float2 dn = make_float2(bd.x + a1d - a3d, bd.y + a2d + a4d);
            if (m == 0) {
                G0[0] = up;
            } else {
                SGDG[(m - 1) * SGSTRIDE] =
                    make_float4(up.x + dn.x, up.y + dn.y,
                                up.y - dn.y, up.x - dn.x);
            }
        }
    }
    __syncthreads();

    // ---- Phase C: tile-4 units (low reg pressure -> pipelined LDS)
    //      crop: 18 units (ut 0..8, vb 0..1), window: nu*nv units ----
    const int nunits = 18 + nu * nv;
    float lmax = 0.0f;
    const char* wp = (const char*)Wp;

    for (int i = 0; ; i++) {
        int t = warp + NWARP * i;
        if (t >= nunits) break;

        bool is_crop = (t < 18);
        int u0, slot;
        if (is_crop) {
            int ut = t >> 1;                // 0..8 -> u0 = 4*ut (u 0..35)
            int vb = t & 1;
            slot = (vb << 5) + lane;        // tcol 0..63
            u0 = ut << 2;
        } else {
            int t2  = t - 18;
            int wvb = t2 / nu;
            int wt  = t2 - wvb * nu;
            int ub  = (wu0 + (wt << 2)) & 255;
            int cu  = (ub + 32) & 255;
            bool u_in = (cu <= 60);
            bool v_in = (wvb == 0) ? vin0 : (wvb == 1) ? vin1 : vin2;
            if (u_in && v_in) continue;     // fully covered by crop units
            int cblk = (wvb == 0) ? cblk0 : (wvb == 1) ? cblk1 : cblk2;
            slot = (v_in ? cblk : (64 + (wvb << 5))) + lane;
            u0 = ub;
        }

        int st0 = (((u0 + 0) & 255) << 4), st1 = (((u0 + 1) & 255) << 4);
        int st2 = (((u0 + 2) & 255) << 4), st3 = (((u0 + 3) & 255) << 4);
        int o0 = st0, o1 = st1, o2 = st2, o3 = st3;
        ull c0 = 0, s0 = 0, c1 = 0, s1 = 0;
        ull c2 = 0, s2 = 0, c3 = 0, s3 = 0;

        const char* gp = (const char*)(SGDG + slot);
        #pragma unroll 4
        for (int m = 1; m <= 24; m++) {
            ulonglong2 gsd = *(const ulonglong2*)gp;
            gp += SGSTRIDE * 16;
            ulonglong2 w0 = *(const ulonglong2*)(wp + o0);
            ulonglong2 w1 = *(const ulonglong2*)(wp + o1);
            ulonglong2 w2 = *(const ulonglong2*)(wp + o2);
            ulonglong2 w3 = *(const ulonglong2*)(wp + o3);
            FMA2(c0, w0.x, gsd.x, c0); FMA2(s0, w0.y, gsd.y, s0);
            FMA2(c1, w1.x, gsd.x, c1); FMA2(s1, w1.y, gsd.y, s1);
            FMA2(c2, w2.x, gsd.x, c2); FMA2(s2, w2.y, gsd.y, s2);
            FMA2(c3, w3.x, gsd.x, c3); FMA2(s3, w3.y, gsd.y, s3);
            o0 = (o0 + st0) & 4095;
            o1 = (o1 + st1) & 4095;
            o2 = (o2 + st2) & 4095;
            o3 = (o3 + st3) & 4095;
        }

        float2 g0 = G0[slot];
        #pragma unroll
        for (int j = 0; j < 4; j++) {
            ull cj = (j == 0) ? c0 : (j == 1) ? c1 : (j == 2) ? c2 : c3;
            ull sj = (j == 0) ? s0 : (j == 1) ? s1 : (j == 2) ? s2 : s3;
            float2 ac = u2f2(cj);
            float2 as = u2f2(sj);
            float t1r = g0.x + ac.x, t1i = g0.y + ac.y;
            float orx = t1r - as.x, oix = t1i + as.y;   // out(u)
            float p2a = fmaf(orx, orx, oix * oix);
            lmax = fmaxf(lmax, p2a);
            if (is_crop) {
                float prx = t1r + as.x, pix = t1i - as.y; // out(256-u)
                float p2b = fmaf(prx, prx, pix * pix);
                lmax = fmaxf(lmax, p2b);
                int u  = u0 + j;
                int sa = (u + 32) & 255;
                if (sa < 64) crop[(sa << 6) + slot] = p2a;
                int sb = (32 - u) & 255;
                if (sb < 64) crop[(sb << 6) + slot] = p2b;
            }
        }
    }

    // ---- CTA max reduction (16 warps) ----
    #pragma unroll
    for (int o = 16; o > 0; o >>= 1)
        lmax = fmaxf(lmax, __shfl_xor_sync(0xFFFFFFFFu, lmax, o));
    if (lane == 0) red[warp] = lmax;
    __syncthreads();
    if (warp == 0) {
        float m = (lane < NWARP) ? red[lane] : 0.0f;
        #pragma unroll
        for (int o = 8; o > 0; o >>= 1)
            m = fmaxf(m, __shfl_xor_sync(0xFFFFFFFFu, m, o));
        if (lane == 0) red[0] = m;
    }
    __syncthreads();
    const float maxv = red[0];

    // ---- epilogue: atomic-accumulate (psf/max * A + bg) * mask into out[b] ----
    const float A    = Aa[img];
    const float bg   = Bg[img];
    const float mask = (P[img] > 0.5f) ? 1.0f : 0.0f;
    const float scale = (A / maxv) * mask;
    const float bgm   = bg * mask;
    float* outb = out + (size_t)(img >> 2) * 4096;
    #pragma unroll
    for (int k = 0; k < 8; k++) {
        int idx = tid + k * NT;
        atomicAdd(&outb[idx], fmaf(crop[idx], scale, bgm));
    }
}

extern "C" void kernel_launch(void* const* d_in, const int* in_sizes, int n_in,
                              void* d_out, int out_size)
{
    (void)in_sizes; (void)n_in;
    cudaMemsetAsync(d_out, 0, (size_t)out_size * sizeof(float));
    cudaFuncSetAttribute(render_kernel,
                         cudaFuncAttributeMaxDynamicSharedMemorySize, SM_TOTAL);
    render_kernel<<<NIMG, NT, SM_TOTAL>>>(
        (const float*)d_in[0], (const float*)d_in[1], (const float*)d_in[2],
        (const float*)d_in[3], (const float*)d_in[4], (const float*)d_in[5],
        (const float*)d_in[6], (float*)d_out);
}

// round 15
// speedup vs baseline: 1.3154x; 1.0606x over previous
#include <cuda_runtime.h>
#include <math.h>

#define NIMG 256        // B*N = 64*4
#define NT 512
#define NWARP 16

typedef unsigned long long ull;

// ---- dynamic shared layout (bytes), compact-column SGDG (160 slots) ----
#define SM_CSB  0                    // float2 [49]            = 512 (padded)
#define SM_SDB  (SM_CSB + 512)       // float4 [49][24]        = 18816
#define SM_WT   (SM_SDB + 18816)     // float2 [256]           = 2048
#define SM_WP   (SM_WT + 2048)       // ulonglong2 [768]       = 12288 (3x dup)
#define SM_SGDG (SM_WP + 12288)      // float4 [24][160]       = 61440
#define SM_G0   (SM_SGDG + 61440)    // float2 [160]           = 1280
#define SM_CROP (SM_G0 + 1280)       // float  [4096]          = 16384
#define SM_RED  (SM_CROP + 16384)    // float  [16]            = 64
#define SM_TOTAL (SM_RED + 64)       // 112832 bytes (<114KB for 2 CTAs)

#define SGSTRIDE 160

extern __shared__ char smem_raw[];

#define FMA2(d, a, b, c) \
    asm("fma.rn.f32x2 %0, %1, %2, %3;" : "=l"(d) : "l"(a), "l"(b), "l"(c))

__device__ __forceinline__ float2 u2f2(ull v) {
    float2 r;
    asm("mov.b64 {%0, %1}, %2;" : "=f"(r.x), "=f"(r.y) : "l"(v));
    return r;
}
__device__ __forceinline__ ull splat2(float f) {
    ull r;
    asm("mov.b64 %0, {%1, %1};" : "=l"(r) : "f"(f));
    return r;
}

__device__ __forceinline__ float2 pupil_pt(int a, int b, float x, float y,
                                           float z, const float* __restrict__ ph)
{
    float us = (float)(2 * a - 63) * (1.0f / 47.25f);
    float vs = (float)(2 * b - 63) * (1.0f / 47.25f);
    float R  = sqrtf(us * us + vs * vs);
    if (R > 1.0f) return make_float2(0.0f, 0.0f);
    float prop = sqrtf(fmaxf(1.0f - R * R, 0.0f));
    float psi = ph[a * 64 + b] + prop * z
              - (6.283185307179586f / 256.0f)
                * ((float)(a - 32) * x + (float)(b - 32) * y);
    float sn, cs;
    __sincosf(psi, &sn, &cs);
    return make_float2(cs, sn);
}

__device__ __forceinline__ int qe_of(int m) {
    int mm = 2 * m - 1;
    float wrad = 2232.5625f - (float)(mm * mm);
    return min(24, (int)((sqrtf(wrad) - 1.0f) * 0.5f) + 2);
}

__global__ void __launch_bounds__(NT, 2)
render_kernel(const float* __restrict__ X,  const float* __restrict__ Y,
              const float* __restrict__ Z,  const float* __restrict__ Aa,
              const float* __restrict__ Bg, const float* __restrict__ P,
              const float* __restrict__ phase0,
              float* __restrict__ out)
{
    float2*     CsB  = (float2*)    (smem_raw + SM_CSB);
    float4*     SDB  = (float4*)    (smem_raw + SM_SDB);
    float2*     Wt   = (float2*)    (smem_raw + SM_WT);
    ulonglong2* Wp   = (ulonglong2*)(smem_raw + SM_WP);
    float4*     SGDG = (float4*)    (smem_raw + SM_SGDG);
    float2*     G0   = (float2*)    (smem_raw + SM_G0);
    float*      crop = (float*)     (smem_raw + SM_CROP);
    float*      red  = (float*)     (smem_raw + SM_RED);

    const int img  = blockIdx.x;
    const int tid  = threadIdx.x;
    const int lane = tid & 31;
    const int warp = tid >> 5;     // 0..15

    const float x = X[img], y = Y[img], z = Z[img];

    // ---- adaptive window geometry (uniform per CTA) ----
    const int iu = (int)(((unsigned)__float2int_rn(x)) & 255u);
    const int iv = (int)(((unsigned)__float2int_rn(y)) & 255u);
    const float az = fabsf(z);
    const float ru = fminf(40.0f, 12.0f + 6.0f * az);
    const float rv = fminf(48.0f, 12.0f + 6.0f * az);
    const int nu = (int)ceilf(ru * 0.5f);           // u tiles of 4
    const int nv = (int)ceilf(rv * (1.0f / 16.0f)); // v blocks of 32 (<=3)
    const int wu0 = (iu - 2 * nu) & 255;
    const int wv0 = (iv - 16 * nv) & 255;

    // ---- window v-block classification ----
    int cblk0 = (wv0 + 32) & 255;
    int cblk1 = (wv0 + 64) & 255;
    int cblk2 = (wv0 + 96) & 255;
    bool vin0 = (cblk0 <= 32);
    bool vin1 = (cblk1 <= 32);
    bool vin2 = (nv < 3) | (cblk2 <= 32);
    if (nv < 2) vin1 = true;
    int ob0 = -1, ob1 = -1, ob2 = -1, n_out = 0;
    if (!vin0) { ob0 = 0; n_out = 1; }
    if (!vin1) { (n_out == 0 ? ob0 : ob1) = 1; n_out++; }
    if (!vin2) { (n_out == 0 ? ob0 : (n_out == 1 ? ob1 : ob2)) = 2; n_out++; }

    // ---- twiddle tables (packed 3x dup) ----
    if (tid < 256) {
        float s, c;
        sincospif((float)tid * (1.0f / 128.0f), &s, &c);
        Wt[tid] = make_float2(c, s);
        ulonglong2 w2 = make_ulonglong2(splat2(c), splat2(s));
        Wp[tid] = w2; Wp[tid + 256] = w2; Wp[tid + 512] = w2;
    }

    // ---- fused Phase A + SDB ----
    for (int idx = tid; idx < 49 * 25; idx += NT) {
        int r = idx / 25;
        int q = idx - r * 25;               // 0..24
        int a = r + 8;
        if (q == 0) {
            CsB[r] = pupil_pt(a, 32, x, y, z, phase0);
        } else {
            float2 cu = pupil_pt(a, 32 + q, x, y, z, phase0);
            float2 cd = pupil_pt(a, 32 - q, x, y, z, phase0);
            SDB[r * 24 + (q - 1)] = make_float4(cu.x + cd.x, cu.y + cd.y,
                                                cu.y - cd.y, cu.x - cd.x);
        }
    }
    __syncthreads();

    // ---- Phase B: m-paired units, crop + out-of-crop window columns ----
    // unit t: grp = t/13 (0 = crop, 1.. = out-block), k = t%13
    //   k == 0 : m=0 single; k>0 : pair m1=2k-1, m2=2k (shared rotation)
    // final unit (t == 13*(1+n_out)): scalar v=224 column
    const int nb_tot = 13 * (1 + n_out) + 1;
    for (int i = 0; ; i++) {
        int t = warp + NWARP * i;
        if (t >= nb_tot) break;

        if (t < 13 * (1 + n_out)) {
            int grp = t / 13;
            int k   = t - grp * 13;
            bool is_crop = (grp == 0);
            int v, slot_lo;
            if (is_crop) {
                v = lane;                           // 0..31
                slot_lo = 32 + lane;
            } else {
                int wvb = (grp == 1) ? ob0 : (grp == 2) ? ob1 : ob2;
                v = (wv0 + (wvb << 5) + lane) & 255;
                slot_lo = 64 + (wvb << 5) + lane;
            }

            float2 w0 = Wt[v];
            ull CC  = splat2(w0.x), SS  = splat2(w0.y);
            ull RC  = CC,           RS  = SS;
            ull NRS = splat2(-w0.y);
            const ull ZERO = 0;

            if (k == 0) {
                // ---- m = 0 ----
                int qe = qe_of(0);
                ull ACu = 0, ASu = 0;
                const ulonglong2* sup = (const ulonglong2*)(SDB + 24 * 24);
                #pragma unroll 4
                for (int mb = 0; mb < qe; mb++) {
                    ulonglong2 sv = sup[mb];
                    FMA2(ACu, CC, sv.x, ACu);
                    FMA2(ASu, SS, sv.y, ASu);
                    ull t1, t2;
                    FMA2(t1, CC, RC, ZERO); FMA2(t2, CC, RS, ZERO);
                    FMA2(CC, SS, NRS, t1);  FMA2(SS, SS, RC, t2);
                }
                float2 ac = u2f2(ACu), as = u2f2(ASu);
                float2 base = CsB[24];
                float2 glo = make_float2(base.x + ac.x - as.x,
                                         base.y + ac.y + as.y);
                G0[slot_lo] = glo;
                if (is_crop) {
                    float2 ghi = make_float2(base.x + ac.x + as.x,
                                             base.y + ac.y - as.y);
                    G0[32 - v] = (v == 0) ? glo : ghi;
                }
            } else {
                // ---- paired m1 = 2k-1, m2 = 2k ----
                int m1 = 2 * k - 1, m2 = 2 * k;
                int qe = qe_of(m1);            // >= qe_of(m2); extras are 0
                ull A1u = 0, S1u = 0, A1d = 0, S1d = 0;
                ull A2u = 0, S2u = 0, A2d = 0, S2d = 0;
                const ulonglong2* su1 = (const ulonglong2*)(SDB + (24 + m1) * 24);
                const ulonglong2* sd1 = (const ulonglong2*)(SDB + (24 - m1) * 24);
                const ulonglong2* su2 = (const ulonglong2*)(SDB + (24 + m2) * 24);
                const ulonglong2* sd2 = (const ulonglong2*)(SDB + (24 - m2) * 24);
                #pragma unroll 4
                for (int mb = 0; mb < qe; mb++) {
                    ulonglong2 sv1 = su1[mb];
                    ulonglong2 dv1 = sd1[mb];
                    ulonglong2 sv2 = su2[mb];
                    ulonglong2 dv2 = sd2[mb];
                    FMA2(A1u, CC, sv1.x, A1u);
                    FMA2(S1u, SS, sv1.y, S1u);
                    FMA2(A1d, CC, dv1.x, A1d);
                    FMA2(S1d, SS, dv1.y, S1d);
                    FMA2(A2u, CC, sv2.x, A2u);
                    FMA2(S2u, SS, sv2.y, S2u);
                    FMA2(A2d, CC, dv2.x, A2d);
                    FMA2(S2d, SS, dv2.y, S2d);
                    ull t1, t2;
                    FMA2(t1, CC, RC, ZERO); FMA2(t2, CC, RS, ZERO);
                    FMA2(CC, SS, NRS, t1);  FMA2(SS, SS, RC, t2);
                }
                #pragma unroll
                for (int h = 0; h < 2; h++) {
                    int m = h ? m2 : m1;
                    float2 acu = u2f2(h ? A2u : A1u), asu = u2f2(h ? S2u : S1u);
                    float2 acd = u2f2(h ? A2d : A1d), asd = u2f2(h ? S2d : S1d);
                    float2 bu = CsB[24 + m];
                    float2 bd = CsB[24 - m];
                    float2 up_lo = make_float2(bu.x + acu.x - asu.x,
                                               bu.y + acu.y + asu.y);
                    float2 dn_lo = make_float2(bd.x + acd.x - asd.x,
                                               bd.y + acd.y + asd.y);
                    int base = (m - 1) * SGSTRIDE;
                    float4 lo4 = make_float4(up_lo.x + dn_lo.x,
                                             up_lo.y + dn_lo.y,
                                             up_lo.y - dn_lo.y,
                                             up_lo.x - dn_lo.x);
                    SGDG[base + slot_lo] = lo4;
                    if (is_crop) {
                        float2 up_hi = make_float2(bu.x + acu.x + asu.x,
                                                   bu.y + acu.y - asu.y);
                        float2 dn_hi = make_float2(bd.x + acd.x + asd.x,
                                                   bd.y + acd.y - asd.y);
                        float4 hi4 = make_float4(up_hi.x + dn_hi.x,
                                                 up_hi.y + dn_hi.y,
                                                 up_hi.y - dn_hi.y,
                                                 up_hi.x - dn_hi.x);
                        SGDG[base + 32 - v] = (v == 0) ? lo4 : hi4;
                    }
                }
            }
        } else if (lane < 25) {
            // ---- scalar v=224 column (tcol slot 0), lane = m ----
            int m = lane;
            int qe = qe_of(m);
            float2 wv = Wt[224];
            float wc = wv.x, ws = wv.y;
            float rc = wc, rs = ws;
            float a1u = 0, a2u = 0, a3u = 0, a4u = 0;
            float a1d = 0, a2d = 0, a3d = 0, a4d = 0;
            const float4* sup = SDB + (24 + m) * 24;
            const float4* sdn = SDB + (24 - m) * 24;
            for (int q = 0; q < qe; q++) {
                float4 s = sup[q];
                a1u = fmaf(wc, s.x, a1u); a2u = fmaf(wc, s.y, a2u);
                a3u = fmaf(ws, s.z, a3u); a4u = fmaf(ws, s.w, a4u);
                float4 d = sdn[q];
                a1d = fmaf(wc, d.x, a1d); a2d = fmaf(wc, d.y, a2d);
                a3d = fmaf(ws, d.z, a3d); a4d = fmaf(ws, d.w, a4d);
                float nc = fmaf(wc, rc, -(ws * rs));
                float ns = fmaf(wc, rs,  (ws * rc));
                wc = nc; ws = ns;
            }
            float2 bu = CsB[24 + m];
            float2 bd = CsB[24 - m];
            float2 up = make_float2(bu.x + a1u - a3u, bu.y + a2u + a4u);
            float2 dn = make_float2(bd.x + a1d - a3d, bd.y + a2d + a4d);
            if (m == 0) {
                G0[0] = up;
            } else {
                SGDG[(m - 1) * SGSTRIDE] =
                    make_float4(up.x + dn.x, up.y + dn.y,
                                up.y - dn.y, up.x - dn.x);
            }
        }
    }
    __syncthreads();

    // ---- Phase C: tile-4 units, wrap every 2nd m-step via 3x dup table ----
    const int nunits = 18 + nu * nv;
    float lmax = 0.0f;
    const char* wp = (const char*)Wp;

    for (int i = 0; ; i++) {
        int t = warp + NWARP * i;
        if (t >= nunits) break;

        bool is_crop = (t < 18);
        int u0, slot;
        if (is_crop) {
            int ut = t >> 1;                // 0..8 -> u0 = 4*ut (u 0..35)
            int vb = t & 1;
            slot = (vb << 5) + lane;        // tcol 0..63
            u0 = ut << 2;
        } else {
            int t2  = t - 18;
            int wvb = t2 / nu;
            int wt  = t2 - wvb * nu;
            int ub  = (wu0 + (wt << 2)) & 255;
            int cu  = (ub + 32) & 255;
            bool u_in = (cu <= 60);
            bool v_in = (wvb == 0) ? vin0 : (wvb == 1) ? vin1 : vin2;
            if (u_in && v_in) continue;     // fully covered by crop units
            int cblk = (wvb == 0) ? cblk0 : (wvb == 1) ? cblk1 : cblk2;
            slot = (v_in ? cblk : (64 + (wvb << 5))) + lane;
            u0 = ub;
        }

        int st0 = (((u0 + 0) & 255) << 4), st1 = (((u0 + 1) & 255) << 4);
        int st2 = (((u0 + 2) & 255) << 4), st3 = (((u0 + 3) & 255) << 4);
        int o0 = st0, o1 = st1, o2 = st2, o3 = st3;
        ull c0 = 0, s0 = 0, c1 = 0, s1 = 0;
        ull c2 = 0, s2 = 0, c3 = 0, s3 = 0;

        const char* gp = (const char*)(SGDG + slot);
        #pragma unroll 3
        for (int mh = 0; mh < 12; mh++) {
            {
                ulonglong2 gsd = *(const ulonglong2*)gp;
                gp += SGSTRIDE * 16;
                ulonglong2 w0 = *(const ulonglong2*)(wp + o0);
                ulonglong2 w1 = *(const ulonglong2*)(wp + o1);
                ulonglong2 w2 = *(const ulonglong2*)(wp + o2);
                ulonglong2 w3 = *(const ulonglong2*)(wp + o3);
                FMA2(c0, w0.x, gsd.x, c0); FMA2(s0, w0.y, gsd.y, s0);
                FMA2(c1, w1.x, gsd.x, c1); FMA2(s1, w1.y, gsd.y, s1);
                FMA2(c2, w2.x, gsd.x, c2); FMA2(s2, w2.y, gsd.y, s2);
                FMA2(c3, w3.x, gsd.x, c3); FMA2(s3, w3.y, gsd.y, s3);
                o0 += st0; o1 += st1; o2 += st2; o3 += st3;  // <= 8175, in dup
            }
            {
                ulonglong2 gsd = *(const ulonglong2*)gp;
                gp += SGSTRIDE * 16;
                ulonglong2 w0 = *(const ulonglong2*)(wp + o0);
                ulonglong2 w1 = *(const ulonglong2*)(wp + o1);
                ulonglong2 w2 = *(const ulonglong2*)(wp + o2);
                ulonglong2 w3 = *(const ulonglong2*)(wp + o3);
                FMA2(c0, w0.x, gsd.x, c0); FMA2(s0, w0.y, gsd.y, s0);
                FMA2(c1, w1.x, gsd.x, c1); FMA2(s1, w1.y, gsd.y, s1);
                FMA2(c2, w2.x, gsd.x, c2); FMA2(s2, w2.y, gsd.y, s2);
                FMA2(c3, w3.x, gsd.x, c3); FMA2(s3, w3.y, gsd.y, s3);
                o0 = (o0 + st0) & 4095; o1 = (o1 + st1) & 4095;
                o2 = (o2 + st2) & 4095; o3 = (o3 + st3) & 4095;
            }
        }

        float2 g0 = G0[slot];
        #pragma unroll
        for (int j = 0; j < 4; j++) {
            ull cj = (j == 0) ? c0 : (j == 1) ? c1 : (j == 2) ? c2 : c3;
            ull sj = (j == 0) ? s0 : (j == 1) ? s1 : (j == 2) ? s2 : s3;
            float2 ac = u2f2(cj);
            float2 as = u2f2(sj);
            float t1r = g0.x + ac.x, t1i = g0.y + ac.y;
            float orx = t1r - as.x, oix = t1i + as.y;   // out(u)
            float p2a = fmaf(orx, orx, oix * oix);
            lmax = fmaxf(lmax, p2a);
            if (is_crop) {
                float prx = t1r + as.x, pix = t1i - as.y; // out(256-u)
                float p2b = fmaf(prx, prx, pix * pix);
                lmax = fmaxf(lmax, p2b);
                int u  = u0 + j;
                int sa = (u + 32) & 255;
                if (sa < 64) crop[(sa << 6) + slot] = p2a;
                int sb = (32 - u) & 255;
                if (sb < 64) crop[(sb << 6) + slot] = p2b;
            }
        }
    }

    // ---- CTA max reduction (16 warps) ----
    #pragma unroll
    for (int o = 16; o > 0; o >>= 1)
        lmax = fmaxf(lmax, __shfl_xor_sync(0xFFFFFFFFu, lmax, o));
    if (lane == 0) red[warp] = lmax;
    __syncthreads();
    if (warp == 0) {
        float m = (lane < NWARP) ? red[lane] : 0.0f;
        #pragma unroll
        for (int o = 8; o > 0; o >>= 1)
            m = fmaxf(m, __shfl_xor_sync(0xFFFFFFFFu, m, o));
        if (lane == 0) red[0] = m;
    }
    __syncthreads();
    const float maxv = red[0];

    // ---- epilogue: atomic-accumulate (psf/max * A + bg) * mask into out[b] ----
    const float A    = Aa[img];
    const float bg   = Bg[img];
    const float mask = (P[img] > 0.5f) ? 1.0f : 0.0f;
    const float scale = (A / maxv) * mask;
    const float bgm   = bg * mask;
    float* outb = out + (size_t)(img >> 2) * 4096;
    #pragma unroll
    for (int k = 0; k < 8; k++) {
        int idx = tid + k * NT;
        atomicAdd(&outb[idx], fmaf(crop[idx], scale, bgm));
    }
}

extern "C" void kernel_launch(void* const* d_in, const int* in_sizes, int n_in,
                              void* d_out, int out_size)
{
    (void)in_sizes; (void)n_in;
    cudaMemsetAsync(d_out, 0, (size_t)out_size * sizeof(float));
    cudaFuncSetAttribute(render_kernel,
                         cudaFuncAttributeMaxDynamicSharedMemorySize, SM_TOTAL);
    render_kernel<<<NIMG, NT, SM_TOTAL>>>(
        (const float*)d_in[0], (const float*)d_in[1], (const float*)d_in[2],
        (const float*)d_in[3], (const float*)d_in[4], (const float*)d_in[5],
        (const float*)d_in[6], (float*)d_out);
}